// round 1
// baseline (speedup 1.0000x reference)
#include <cuda_runtime.h>
#include <cuda_bf16.h>

// SchNetClassifier — analytically collapsed.
// Only v[:,0,:] is read by the reference, and atom_emb broadcasts a single
// F-vector, so x[b,m,:] == x[:] is constant. The output reduces to:
//   out[b] = Q_b + Q.e + sum_{m=1..N-1} ( sum_d rbf_d(|r_b0 - r_bm|) * c_d + cb )
// with c_d = sum_f Q_f x_f Wc_w[f,d],  cb = sum_f Q_f x_f Wc_b[f],
//      x_g = sum_f e_f Wi_w[g,f] + Wi_b[g].

#define GAMMA_ 10.0f
#define FDIM 16
#define DDIM 20
#define NPTS 512
#define NTHREADS 512

__global__ __launch_bounds__(NTHREADS)
void schnet_kernel(const float* __restrict__ coords,
                   const float* __restrict__ atom_emb,
                   const float* __restrict__ Wc_w,
                   const float* __restrict__ Wc_b,
                   const float* __restrict__ Wi_w,
                   const float* __restrict__ Wi_b,
                   const float* __restrict__ Q_w,
                   const float* __restrict__ Q_b,
                   float* __restrict__ out) {
    __shared__ float x_sh[FDIM];       // x[g] (constant over b,m)
    __shared__ float c_sh[DDIM];       // c_d
    __shared__ float cb_sh;            // cb
    __shared__ float base_sh;          // Q_b + Q.e
    __shared__ float red[NTHREADS / 32];

    const int tid = threadIdx.x;
    const int b  = blockIdx.x;

    // --- stage 1: x[g] = Wi_b[g] + sum_f e[f] * Wi_w[g,f]  (threads 0..15) ---
    if (tid < FDIM) {
        float acc = Wi_b[tid];
        #pragma unroll
        for (int f = 0; f < FDIM; f++)
            acc = fmaf(atom_emb[f], Wi_w[tid * FDIM + f], acc);
        x_sh[tid] = acc;
    }
    __syncthreads();

    // --- stage 2: fold x into Wc via Q (threads 0..21) ---
    if (tid < DDIM) {
        float acc = 0.f;
        #pragma unroll
        for (int f = 0; f < FDIM; f++)
            acc = fmaf(Q_w[f] * x_sh[f], Wc_w[f * DDIM + tid], acc);
        c_sh[tid] = acc;
    } else if (tid == DDIM) {
        float acc = 0.f;
        #pragma unroll
        for (int f = 0; f < FDIM; f++)
            acc = fmaf(Q_w[f] * x_sh[f], Wc_b[f], acc);
        cb_sh = acc;
    } else if (tid == DDIM + 1) {
        float acc = Q_b[0];
        #pragma unroll
        for (int f = 0; f < FDIM; f++)
            acc = fmaf(Q_w[f], atom_emb[f], acc);
        base_sh = acc;
    }
    __syncthreads();

    // --- stage 3: neighbor loop (one m per thread) ---
    const float* C = coords + (size_t)b * NPTS * 3;
    const float x0 = C[0], y0 = C[1], z0 = C[2];

    float acc = 0.f;
    for (int m = tid; m < NPTS; m += NTHREADS) {
        if (m == 0) continue;               // diagonal mask (n==m, n=0)
        float dx = C[m * 3 + 0] - x0;
        float dy = C[m * 3 + 1] - y0;
        float dz = C[m * 3 + 2] - z0;
        float d2 = fmaf(dx, dx, fmaf(dy, dy, dz * dz));
        float adj = d2 > 0.f ? sqrtf(d2) : 0.f;   // match reference semantics
        float s = cb_sh;
        #pragma unroll
        for (int d = 0; d < DDIM; d++) {
            float t = adj - 0.1f * (float)d;
            s = fmaf(__expf(-GAMMA_ * t * t), c_sh[d], s);
        }
        acc += s;
    }

    // --- block reduction: warp shuffle, then cross-warp ---
    #pragma unroll
    for (int off = 16; off > 0; off >>= 1)
        acc += __shfl_xor_sync(0xFFFFFFFFu, acc, off);
    if ((tid & 31) == 0) red[tid >> 5] = acc;
    __syncthreads();
    if (tid < NTHREADS / 32) {
        float v = red[tid];
        #pragma unroll
        for (int off = NTHREADS / 64; off > 0; off >>= 1)
            v += __shfl_xor_sync(0xFFFFFFFFu, v, off);
        if (tid == 0) out[b] = base_sh + v;
    }
}

extern "C" void kernel_launch(void* const* d_in, const int* in_sizes, int n_in,
                              void* d_out, int out_size) {
    const float* coords   = (const float*)d_in[0];
    const float* atom_emb = (const float*)d_in[1];
    const float* Wc_w     = (const float*)d_in[2];
    const float* Wc_b     = (const float*)d_in[3];
    const float* Wi_w     = (const float*)d_in[4];
    const float* Wi_b     = (const float*)d_in[5];
    const float* Q_w      = (const float*)d_in[6];
    const float* Q_b      = (const float*)d_in[7];
    float* out = (float*)d_out;

    const int B = in_sizes[0] / (NPTS * 3);
    schnet_kernel<<<B, NTHREADS>>>(coords, atom_emb, Wc_w, Wc_b,
                                   Wi_w, Wi_b, Q_w, Q_b, out);
}

// round 2
// speedup vs baseline: 1.1010x; 1.1010x over previous
#include <cuda_runtime.h>
#include <cuda_bf16.h>

// SchNetClassifier — analytically collapsed, latency-optimized.
//   out[b] = Q_b + Q.e + sum_{m=1..N-1} ( sum_d rbf_d(|r_b0 - r_bm|) * c_d + cb )
// with c_d = sum_f (Q_f x_f) Wc_w[f,d],  cb = sum_f (Q_f x_f) Wc_b[f],
//      x_g = sum_f e_f Wi_w[g,f] + Wi_b[g].
//
// All global loads are issued before any compute/barrier so the single
// DRAM round-trip latency is paid once, fully overlapped (MLP >> 4).

#define GAMMA_ 10.0f
#define FDIM 16
#define DDIM 20
#define NPTS 512
#define NTHREADS 512

__global__ __launch_bounds__(NTHREADS)
void schnet_kernel(const float* __restrict__ coords,
                   const float* __restrict__ atom_emb,
                   const float* __restrict__ Wc_w,
                   const float* __restrict__ Wc_b,
                   const float* __restrict__ Wi_w,
                   const float* __restrict__ Wi_b,
                   const float* __restrict__ Q_w,
                   const float* __restrict__ Q_b,
                   float* __restrict__ out) {
    __shared__ float y_sh[FDIM];       // y_f = Q_f * x_f
    __shared__ float c_sh[DDIM];       // c_d
    __shared__ float cb_sh;            // cb
    __shared__ float base_sh;          // Q_b + Q.e
    __shared__ float red[NTHREADS / 32];

    const int tid = threadIdx.x;
    const int b  = blockIdx.x;

    // ---------------- front-batched global loads (no dependencies) --------
    const float* C = coords + (size_t)b * NPTS * 3;

    // every thread: its own coordinate triple + origin triple
    const float cx = C[tid * 3 + 0];
    const float cy = C[tid * 3 + 1];
    const float cz = C[tid * 3 + 2];
    const float ox = C[0], oy = C[1], oz = C[2];

    // stage-1 operands (threads 0..15): full atom_emb, own Wi row, bias, Q_f
    float e_r[FDIM], wi_r[FDIM];
    float bias_r = 0.f, q_r = 0.f;
    if (tid < FDIM) {
        #pragma unroll
        for (int f = 0; f < FDIM; f++) e_r[f]  = atom_emb[f];
        #pragma unroll
        for (int f = 0; f < FDIM; f++) wi_r[f] = Wi_w[tid * FDIM + f];
        bias_r = Wi_b[tid];
        q_r    = Q_w[tid];
    }

    // stage-2 operands (threads 0..19): own Wc_w column
    float wc_r[FDIM];
    if (tid < DDIM) {
        #pragma unroll
        for (int f = 0; f < FDIM; f++) wc_r[f] = Wc_w[f * DDIM + tid];
    }
    // thread 20: Wc_b ; thread 21: Q_w, atom_emb, Q_b (for cb / base)
    float wcb_r[FDIM], qa_r[FDIM], ea_r[FDIM];
    float qb_r = 0.f;
    if (tid == DDIM) {
        #pragma unroll
        for (int f = 0; f < FDIM; f++) wcb_r[f] = Wc_b[f];
    } else if (tid == DDIM + 1) {
        qb_r = Q_b[0];
        #pragma unroll
        for (int f = 0; f < FDIM; f++) qa_r[f] = Q_w[f];
        #pragma unroll
        for (int f = 0; f < FDIM; f++) ea_r[f] = atom_emb[f];
    }

    // ---------------- stage 1: y_f = Q_f * (Wi_b[f] + e . Wi_w[f,:]) ------
    if (tid < FDIM) {
        float acc = bias_r;
        #pragma unroll
        for (int f = 0; f < FDIM; f++)
            acc = fmaf(e_r[f], wi_r[f], acc);
        y_sh[tid] = q_r * acc;
    }
    // base has no dependency on y — compute before the barrier
    if (tid == DDIM + 1) {
        float acc = qb_r;
        #pragma unroll
        for (int f = 0; f < FDIM; f++)
            acc = fmaf(qa_r[f], ea_r[f], acc);
        base_sh = acc;
    }
    __syncthreads();

    // ---------------- stage 2: c_d, cb (pure register/shared math) --------
    if (tid < DDIM) {
        float acc = 0.f;
        #pragma unroll
        for (int f = 0; f < FDIM; f++)
            acc = fmaf(y_sh[f], wc_r[f], acc);
        c_sh[tid] = acc;
    } else if (tid == DDIM) {
        float acc = 0.f;
        #pragma unroll
        for (int f = 0; f < FDIM; f++)
            acc = fmaf(y_sh[f], wcb_r[f], acc);
        cb_sh = acc;
    }
    __syncthreads();

    // ---------------- stage 3: one neighbor per thread --------------------
    float acc = 0.f;
    if (tid != 0) {                       // diagonal mask (n==m, n=0)
        const float dx = cx - ox;
        const float dy = cy - oy;
        const float dz = cz - oz;
        const float d2  = fmaf(dx, dx, fmaf(dy, dy, dz * dz));
        const float adj = d2 > 0.f ? sqrtf(d2) : 0.f;
        float s = cb_sh;
        #pragma unroll
        for (int d = 0; d < DDIM; d++) {
            const float t = adj - 0.1f * (float)d;
            s = fmaf(__expf(-GAMMA_ * t * t), c_sh[d], s);
        }
        acc = s;
    }

    // ---------------- block reduction -------------------------------------
    #pragma unroll
    for (int off = 16; off > 0; off >>= 1)
        acc += __shfl_xor_sync(0xFFFFFFFFu, acc, off);
    if ((tid & 31) == 0) red[tid >> 5] = acc;
    __syncthreads();
    if (tid < NTHREADS / 32) {
        float v = red[tid];
        #pragma unroll
        for (int off = NTHREADS / 64; off > 0; off >>= 1)
            v += __shfl_xor_sync(0xFFFFFFFFu, v, off);
        if (tid == 0) out[b] = base_sh + v;
    }
}

extern "C" void kernel_launch(void* const* d_in, const int* in_sizes, int n_in,
                              void* d_out, int out_size) {
    const float* coords   = (const float*)d_in[0];
    const float* atom_emb = (const float*)d_in[1];
    const float* Wc_w     = (const float*)d_in[2];
    const float* Wc_b     = (const float*)d_in[3];
    const float* Wi_w     = (const float*)d_in[4];
    const float* Wi_b     = (const float*)d_in[5];
    const float* Q_w      = (const float*)d_in[6];
    const float* Q_b      = (const float*)d_in[7];
    float* out = (float*)d_out;

    const int B = in_sizes[0] / (NPTS * 3);
    schnet_kernel<<<B, NTHREADS>>>(coords, atom_emb, Wc_w, Wc_b,
                                   Wi_w, Wi_b, Q_w, Q_b, out);
}